// round 15
// baseline (speedup 1.0000x reference)
#include <cuda_runtime.h>

// LocalCosineSimilarity v5 — float2-per-lane, 4 warps/CTA, 2-deep prefetch.
// Horizontal 11-tap via pair-sum warp scan; vertical 11-tap via per-lane
// float2 smem ring + register running sums. Warp-autonomous (no CTA barriers
// in steady state).

#define IMG_W   1024
#define IMG_H   1024
#define KW      11
#define HALO    5
#define OL      26                 // output lanes per warp (2 cols each)
#define WC      (OL * 2)           // 52 output cols per warp
#define NWARP   4
#define NT      (NWARP * 32)       // 128
#define CTAC    (NWARP * WC)       // 208 output cols per CTA
#define CH      32                 // output rows per CTA
#define NR      (CH + 2 * HALO)    // 42 input rows streamed
#define FULLM   0xffffffffu

__global__ void __launch_bounds__(NT, 8)
lcs_v5_kernel(const float* __restrict__ xg, const float* __restrict__ yg,
              float* __restrict__ outg)
{
    __shared__ float2 ring[NWARP][KW][3][OL];   // 27.5 KB

    const int lane = threadIdx.x & 31;
    const int w    = threadIdx.x >> 5;

    const int cta_base = min((int)blockIdx.x * CTAC, IMG_W - CTAC); // clamp last
    const int out_base = cta_base + w * WC;        // warp's first output col
    const int gy0      = blockIdx.y * CH;
    const int b        = blockIdx.z;

    const size_t HW = (size_t)IMG_W * IMG_H;
    const float* xb = xg + (size_t)b * 3 * HW;
    const float* yb = yg + (size_t)b * 3 * HW;
    float* outb = outg + (size_t)b * HW;

    // lane loads global cols c0, c0+1 (even-aligned for float2)
    const int  c0     = out_base - 6 + 2 * lane;
    const bool colv   = (c0 >= 0) && (c0 + 1 < IMG_W);   // exact zero-padding
    const bool active = lane < OL;

    {   // zero this warp's ring
        float2* rp = &ring[w][0][0][0];
        const float2 z = make_float2(0.f, 0.f);
        for (int i = lane; i < KW * 3 * OL; i += 32) rp[i] = z;
    }
    __syncwarp();

    const float* xp = xb + (colv ? c0 : 0);
    const float* yp = yb + (colv ? c0 : 0);

    // channel-reduced products for the lane's 2 pixels of input row r
    auto loadrow = [&](int r, float2& pxx, float2& pyy, float2& pxy) {
        pxx = pyy = pxy = make_float2(0.f, 0.f);
        const int gy = gy0 - HALO + r;
        if (r < NR && (unsigned)gy < (unsigned)IMG_H && colv) {
            const size_t o = (size_t)gy * IMG_W;
            #pragma unroll
            for (int ch = 0; ch < 3; ++ch) {
                const float2 xv = *reinterpret_cast<const float2*>(xp + (size_t)ch * HW + o);
                const float2 yv = *reinterpret_cast<const float2*>(yp + (size_t)ch * HW + o);
                pxx.x = fmaf(xv.x, xv.x, pxx.x); pxx.y = fmaf(xv.y, xv.y, pxx.y);
                pyy.x = fmaf(yv.x, yv.x, pyy.x); pyy.y = fmaf(yv.y, yv.y, pyy.y);
                pxy.x = fmaf(xv.x, yv.x, pxy.x); pxy.y = fmaf(xv.y, yv.y, pxy.y);
            }
        }
    };

    // Horizontal 11-tap. Loaded idx q <-> global col out_base-6+q.
    // E[l] = inclusive scan of pair sums = sum v[0..2l+1].
    // lane l outputs cols out_base+2l, out_base+2l+1:
    //   H0 = sum v[2l+1..2l+11] = E[l+5] - E[l] + v.y[l]
    //   H1 = sum v[2l+2..2l+12] = E[l+6] - v.y[l+6] - E[l]
    auto hwin = [&](const float2 v, float2& H) {
        float E = v.x + v.y;
        #pragma unroll
        for (int o = 1; o < 32; o <<= 1) {
            const float t = __shfl_up_sync(FULLM, E, o);
            if (lane >= o) E += t;
        }
        const float E5  = __shfl_down_sync(FULLM, E, 5);
        const float E6  = __shfl_down_sync(FULLM, E, 6);
        const float vy6 = __shfl_down_sync(FULLM, v.y, 6);
        H.x = E5 - E + v.y;
        H.y = E6 - vy6 - E;
    };

    // 2-deep prefetch pipeline
    float2 n0xx, n0yy, n0xy, n1xx, n1yy, n1xy;
    loadrow(0, n0xx, n0yy, n0xy);
    loadrow(1, n1xx, n1yy, n1xy);

    float2 axx = make_float2(0.f, 0.f), ayy = axx, axy = axx;
    int slot = 0;

    #pragma unroll 1
    for (int r = 0; r < NR; ++r) {
        const float2 cxx = n0xx, cyy = n0yy, cxy = n0xy;
        n0xx = n1xx; n0yy = n1yy; n0xy = n1xy;
        loadrow(r + 2, n1xx, n1yy, n1xy);       // in flight ~2 loop bodies

        float2 Hxx, Hyy, Hxy;
        hwin(cxx, Hxx);
        hwin(cyy, Hyy);
        hwin(cxy, Hxy);

        if (active) {
            float2 o0 = ring[w][slot][0][lane];
            axx.x += Hxx.x - o0.x;  axx.y += Hxx.y - o0.y;
            ring[w][slot][0][lane] = Hxx;

            float2 o1 = ring[w][slot][1][lane];
            ayy.x += Hyy.x - o1.x;  ayy.y += Hyy.y - o1.y;
            ring[w][slot][1][lane] = Hyy;

            float2 o2 = ring[w][slot][2][lane];
            axy.x += Hxy.x - o2.x;  axy.y += Hxy.y - o2.y;
            ring[w][slot][2][lane] = Hxy;

            if (r >= 2 * HALO) {
                const int ro = gy0 + r - 2 * HALO;
                float2 o;
                o.x = axy.x / (sqrtf(axx.x) * sqrtf(ayy.x) + 1e-6f);
                o.y = axy.y / (sqrtf(axx.y) * sqrtf(ayy.y) + 1e-6f);
                *reinterpret_cast<float2*>(outb + (size_t)ro * IMG_W + out_base + 2 * lane) = o;
            }
        }
        if (++slot == KW) slot = 0;
    }
}

extern "C" void kernel_launch(void* const* d_in, const int* in_sizes, int n_in,
                              void* d_out, int out_size)
{
    const float* x = (const float*)d_in[0];
    const float* y = (const float*)d_in[1];
    float* out = (float*)d_out;

    dim3 grid((IMG_W + CTAC - 1) / CTAC,   // 5 (last clamped, overlap benign)
              IMG_H / CH,                  // 32
              8);                          // batch -> 1280 CTAs, 5120 warps
    lcs_v5_kernel<<<grid, NT>>>(x, y, out);
}

// round 17
// speedup vs baseline: 1.1999x; 1.1999x over previous
#include <cuda_runtime.h>

// LocalCosineSimilarity — warp-autonomous streaming box filter, v6.
// Identical to the 78.3us v3 kernel except CH 64 -> 32: doubles the grid to
// 3072 CTAs so residency reaches the 13-CTA/SM register cap (occupancy was
// grid-limited at 59%).

#define IMG_W  1024
#define IMG_H  1024
#define KW     11
#define HALO   5
#define WCOLS  22                 // output cols per warp (lanes 0..21)
#define NWARP  4
#define NT     (NWARP * 32)       // 128
#define CTAC   (NWARP * WCOLS)    // 88 output cols per CTA
#define CH     32                 // output rows per CTA
#define NR     (CH + 2 * HALO)    // 42 input rows streamed

__global__ void __launch_bounds__(NT, 8)
lcs_v6_kernel(const float* __restrict__ xg, const float* __restrict__ yg,
              float* __restrict__ outg)
{
    __shared__ float ring[KW][3][CTAC];   // 11.6 KB; each lane owns one column

    const int tid  = threadIdx.x;
    const int lane = tid & 31;
    const int w    = tid >> 5;

    const int base = blockIdx.x * CTAC + w * WCOLS;   // first output col of warp
    const int gy0  = blockIdx.y * CH;
    const int b    = blockIdx.z;

    const size_t HW = (size_t)IMG_W * IMG_H;
    const float* xb = xg + (size_t)b * 3 * HW;
    const float* yb = yg + (size_t)b * 3 * HW;
    float* outb = outg + (size_t)b * HW;

    const int  c_in   = base - HALO + lane;            // col this lane loads
    const bool colv   = (unsigned)c_in < (unsigned)IMG_W;
    const int  c_out  = base + lane;                   // col this lane outputs
    const bool active = (lane < WCOLS) && ((unsigned)c_out < (unsigned)IMG_W);
    const int  rcol   = w * WCOLS + lane;              // ring column (lane<WCOLS)

    // zero the ring (each lane only touches its own column afterwards)
    for (int i = tid; i < KW * 3 * CTAC; i += NT)
        ((float*)ring)[i] = 0.f;
    __syncthreads();   // only barrier in the kernel

    const float* xp = xb + (colv ? c_in : 0);
    const float* yp = yb + (colv ? c_in : 0);

    // ---- prefetch row 0 products ----
    float nxx, nyy, nxy;
    {
        const int gy = gy0 - HALO;
        nxx = nyy = nxy = 0.f;
        if (colv && (unsigned)gy < (unsigned)IMG_H) {
            const size_t o = (size_t)gy * IMG_W;
            #pragma unroll
            for (int ch = 0; ch < 3; ++ch) {
                const float xv = __ldg(xp + (size_t)ch * HW + o);
                const float yv = __ldg(yp + (size_t)ch * HW + o);
                nxx = fmaf(xv, xv, nxx);
                nyy = fmaf(yv, yv, nyy);
                nxy = fmaf(xv, yv, nxy);
            }
        }
    }

    float sxx = 0.f, syy = 0.f, sxy = 0.f;
    int slot = 0;

    #pragma unroll 2
    for (int r = 0; r < NR; ++r) {
        // consume prefetched row r
        const float pxx = nxx, pyy = nyy, pxy = nxy;

        // ---- prefetch row r+1 (overlaps the shuffle trees) ----
        nxx = nyy = nxy = 0.f;
        {
            const int gy = gy0 - HALO + r + 1;
            if ((r + 1 < NR) && colv && (unsigned)gy < (unsigned)IMG_H) {
                const size_t o = (size_t)gy * IMG_W;
                #pragma unroll
                for (int ch = 0; ch < 3; ++ch) {
                    const float xv = __ldg(xp + (size_t)ch * HW + o);
                    const float yv = __ldg(yp + (size_t)ch * HW + o);
                    nxx = fmaf(xv, xv, nxx);
                    nyy = fmaf(yv, yv, nyy);
                    nxy = fmaf(xv, yv, nxy);
                }
            }
        }

        // ---- horizontal 11-tap window tree: h[l] = sum v[l..l+10] ----
        const float a0 = pxx + __shfl_down_sync(0xffffffffu, pxx, 1);
        const float a1 = pyy + __shfl_down_sync(0xffffffffu, pyy, 1);
        const float a2 = pxy + __shfl_down_sync(0xffffffffu, pxy, 1);
        const float t0 = a0 + __shfl_down_sync(0xffffffffu, a0, 2);
        const float t1 = a1 + __shfl_down_sync(0xffffffffu, a1, 2);
        const float t2 = a2 + __shfl_down_sync(0xffffffffu, a2, 2);
        const float c0 = t0 + __shfl_down_sync(0xffffffffu, t0, 4);
        const float c1 = t1 + __shfl_down_sync(0xffffffffu, t1, 4);
        const float c2 = t2 + __shfl_down_sync(0xffffffffu, t2, 4);
        const float hxx = c0 + __shfl_down_sync(0xffffffffu, a0, 8)
                             + __shfl_down_sync(0xffffffffu, pxx, 10);
        const float hyy = c1 + __shfl_down_sync(0xffffffffu, a1, 8)
                             + __shfl_down_sync(0xffffffffu, pyy, 10);
        const float hxy = c2 + __shfl_down_sync(0xffffffffu, a2, 8)
                             + __shfl_down_sync(0xffffffffu, pxy, 10);

        // ---- vertical sliding window + finalize ----
        if (active) {
            sxx += hxx - ring[slot][0][rcol];  ring[slot][0][rcol] = hxx;
            syy += hyy - ring[slot][1][rcol];  ring[slot][1][rcol] = hyy;
            sxy += hxy - ring[slot][2][rcol];  ring[slot][2][rcol] = hxy;

            if (r >= 2 * HALO) {
                const int ro = gy0 + r - 2 * HALO;
                outb[(size_t)ro * IMG_W + c_out] =
                    sxy / (sqrtf(sxx) * sqrtf(syy) + 1e-6f);
            }
        }
        if (++slot == KW) slot = 0;
    }
}

extern "C" void kernel_launch(void* const* d_in, const int* in_sizes, int n_in,
                              void* d_out, int out_size)
{
    const float* x = (const float*)d_in[0];
    const float* y = (const float*)d_in[1];
    float* out = (float*)d_out;

    dim3 grid((IMG_W + CTAC - 1) / CTAC,   // 12
              IMG_H / CH,                  // 32
              8);                          // batch -> 3072 CTAs
    lcs_v6_kernel<<<grid, NT>>>(x, y, out);
}